// round 9
// baseline (speedup 1.0000x reference)
#include <cuda_runtime.h>
#include <cstdint>
#include <cstddef>

// Problem constants (fixed shapes for this problem)
#define S_MAX   4096
#define D_DIM   256
#define NH      8
#define HD      32
#define H_DIM   256

// ---------------- device scratch (no cudaMalloc allowed) ----------------
__device__ float g_q[S_MAX * H_DIM];              // q = queries@Wq + bq
__device__ float g_qk[S_MAX * NH * D_DIM];        // qk[s][h][j]
__device__ float g_qb[S_MAX * NH];                // qb[s][h]
__device__ float g_Ahat[S_MAX * NH * D_DIM];      // A/denom
__device__ float g_pooled[S_MAX * H_DIM];
__device__ int   g_off[S_MAX + 1];

// ---------------- bulk-async + mbarrier helpers ----------------
#define MBAR_INIT(addr, count) \
    asm volatile("mbarrier.init.shared.b64 [%0], %1;" :: "r"(addr), "r"(count) : "memory")
#define MBAR_EXPECT_TX(addr, bytes) \
    asm volatile("mbarrier.arrive.expect_tx.shared.b64 _, [%0], %1;" :: "r"(addr), "r"(bytes) : "memory")

__device__ __forceinline__ void mbar_wait(uint32_t mbar, uint32_t parity) {
    asm volatile(
        "{\n\t"
        ".reg .pred P1;\n\t"
        "WAIT_%=:\n\t"
        "mbarrier.try_wait.parity.acquire.cta.shared::cta.b64 P1, [%0], %1, 0x989680;\n\t"
        "@P1 bra DONE_%=;\n\t"
        "bra WAIT_%=;\n\t"
        "DONE_%=:\n\t"
        "}"
        :: "r"(mbar), "r"(parity) : "memory");
}
__device__ __forceinline__ void bulk_g2s(uint32_t dst, const void* src,
                                         uint32_t bytes, uint32_t mbar) {
    asm volatile(
        "cp.async.bulk.shared::cta.global.mbarrier::complete_tx::bytes [%0], [%1], %2, [%3];"
        :: "r"(dst), "l"(src), "r"(bytes), "r"(mbar) : "memory");
}

// ---------------- tf32 3x-split helpers ----------------
__device__ __forceinline__ void tf32_split(float x, uint32_t& hi, uint32_t& lo) {
    asm("cvt.rna.tf32.f32 %0, %1;" : "=r"(hi) : "f"(x));
    float r = x - __uint_as_float(hi);
    asm("cvt.rna.tf32.f32 %0, %1;" : "=r"(lo) : "f"(r));
}
__device__ __forceinline__ void split4(float4 v, uint4& h, uint4& l) {
    tf32_split(v.x, h.x, l.x); tf32_split(v.y, h.y, l.y);
    tf32_split(v.z, h.z, l.z); tf32_split(v.w, h.w, l.w);
}
__device__ __forceinline__ void mma_tf32(float* c, const uint32_t* a, const uint32_t* b) {
    asm("mma.sync.aligned.m16n8k8.row.col.f32.tf32.tf32.f32 "
        "{%0,%1,%2,%3}, {%4,%5,%6,%7}, {%8,%9}, {%0,%1,%2,%3};"
        : "+f"(c[0]), "+f"(c[1]), "+f"(c[2]), "+f"(c[3])
        : "r"(a[0]), "r"(a[1]), "r"(a[2]), "r"(a[3]),
          "r"(b[0]), "r"(b[1]));
}
__device__ __forceinline__ void mma3(float* c, const uint32_t* ah, const uint32_t* al,
                                     const uint32_t* bh, const uint32_t* bl) {
    mma_tf32(c, ah, bh);
    mma_tf32(c, ah, bl);
    mma_tf32(c, al, bh);
}

// ---------------- K0: segment offsets via binary search (idx sorted) ----
__global__ void k_offsets(const int* __restrict__ map, int N, int S) {
    int s = blockIdx.x * blockDim.x + threadIdx.x;
    if (s > S) return;
    int lo = 0, hi = N;
    while (lo < hi) {
        int mid = (lo + hi) >> 1;
        if (map[mid] < s) lo = mid + 1; else hi = mid;
    }
    g_off[s] = lo;
}

// ---------- tensor GEMM (3xTF32, pre-split smem): C = A@B + bias --------
__global__ void __launch_bounds__(256)
k_gemm_tf32(const float* __restrict__ A, const float* __restrict__ B,
            const float* __restrict__ bias, float* __restrict__ C,
            int M, int K, int N) {
    __shared__ uint32_t Ah[64][36], Al[64][36];   // m-major: bank 4*gid+tig
    __shared__ uint32_t Bh[32][72], Bl[32][72];   // k-major: bank 8*tig+gid
    int t = threadIdx.x;
    int lane = t & 31, w = t >> 5;
    int gid = lane >> 2, tig = lane & 3;
    int wm = w & 1, wn = w >> 1;
    int bm = blockIdx.x * 64, bn = blockIdx.y * 64;
    int ar = t >> 2, ac = (t & 3) * 8;
    int br = t >> 3, bc = (t & 7) * 8;

    float c[2][2][4] = {};
    float4 ra0, ra1, rb0, rb1;

    ra0 = *(const float4*)&A[(size_t)(bm + ar) * K + ac];
    ra1 = *(const float4*)&A[(size_t)(bm + ar) * K + ac + 4];
    rb0 = *(const float4*)&B[(size_t)br * N + bn + bc];
    rb1 = *(const float4*)&B[(size_t)br * N + bn + bc + 4];

    int nc = K / 32;
    for (int ch = 0; ch < nc; ch++) {
        if (ch > 0) __syncthreads();
        {
            uint4 h, l;
            split4(ra0, h, l);
            *(uint4*)&Ah[ar][ac] = h;     *(uint4*)&Al[ar][ac] = l;
            split4(ra1, h, l);
            *(uint4*)&Ah[ar][ac + 4] = h; *(uint4*)&Al[ar][ac + 4] = l;
            split4(rb0, h, l);
            *(uint4*)&Bh[br][bc] = h;     *(uint4*)&Bl[br][bc] = l;
            split4(rb1, h, l);
            *(uint4*)&Bh[br][bc + 4] = h; *(uint4*)&Bl[br][bc + 4] = l;
        }
        __syncthreads();
        if (ch + 1 < nc) {
            int k0 = (ch + 1) * 32;
            ra0 = *(const float4*)&A[(size_t)(bm + ar) * K + k0 + ac];
            ra1 = *(const float4*)&A[(size_t)(bm + ar) * K + k0 + ac + 4];
            rb0 = *(const float4*)&B[(size_t)(k0 + br) * N + bn + bc];
            rb1 = *(const float4*)&B[(size_t)(k0 + br) * N + bn + bc + 4];
        }
#pragma unroll
        for (int ks = 0; ks < 4; ks++) {
            int k8 = ks * 8;
            uint32_t ah[2][4], al[2][4], bh[2][2], bl[2][2];
#pragma unroll
            for (int ma = 0; ma < 2; ma++) {
                int m0 = wm * 32 + ma * 16 + gid;
                ah[ma][0] = Ah[m0][k8 + tig];     al[ma][0] = Al[m0][k8 + tig];
                ah[ma][1] = Ah[m0 + 8][k8 + tig]; al[ma][1] = Al[m0 + 8][k8 + tig];
                ah[ma][2] = Ah[m0][k8 + tig + 4]; al[ma][2] = Al[m0][k8 + tig + 4];
                ah[ma][3] = Ah[m0 + 8][k8 + tig + 4]; al[ma][3] = Al[m0 + 8][k8 + tig + 4];
            }
#pragma unroll
            for (int na = 0; na < 2; na++) {
                int n0 = wn * 16 + na * 8 + gid;
                bh[na][0] = Bh[k8 + tig][n0];     bl[na][0] = Bl[k8 + tig][n0];
                bh[na][1] = Bh[k8 + tig + 4][n0]; bl[na][1] = Bl[k8 + tig + 4][n0];
            }
#pragma unroll
            for (int ma = 0; ma < 2; ma++)
#pragma unroll
                for (int na = 0; na < 2; na++)
                    mma3(c[ma][na], ah[ma], al[ma], bh[na], bl[na]);
        }
    }

#pragma unroll
    for (int ma = 0; ma < 2; ma++)
#pragma unroll
        for (int na = 0; na < 2; na++) {
            int row = bm + wm * 32 + ma * 16 + gid;
            int col = bn + wn * 16 + na * 8 + 2 * tig;
            float2 bv = *(const float2*)&bias[col];
            float2 o0; o0.x = c[ma][na][0] + bv.x; o0.y = c[ma][na][1] + bv.y;
            float2 o1; o1.x = c[ma][na][2] + bv.x; o1.y = c[ma][na][3] + bv.y;
            *(float2*)&C[(size_t)row * N + col]       = o0;
            *(float2*)&C[(size_t)(row + 8) * N + col] = o1;
        }
}

// ---------- K2 tensor: qk[s][h][j] = Q_h[s,:] . Wk_h[j,:]  (K=32) -------
__global__ void __launch_bounds__(256)
k_qk_tf32(const float* __restrict__ Wkv, const float* __restrict__ bkv) {
    __shared__ uint32_t Ah[64][36], Al[64][36];   // q slice  [s][d]
    __shared__ uint32_t Nh[64][36], Nl[64][36];   // Wk slice [j][d]
    int t = threadIdx.x;
    int lane = t & 31, w = t >> 5;
    int gid = lane >> 2, tig = lane & 3;
    int wm = w & 1, wn = w >> 1;
    int bm = blockIdx.x * 64, bnj = blockIdx.y * 64, h = blockIdx.z;
    int r = t >> 2, cq = (t & 3) * 8;

    {
        float4 v0 = *(const float4*)&g_q[(size_t)(bm + r) * H_DIM + h * HD + cq];
        float4 v1 = *(const float4*)&g_q[(size_t)(bm + r) * H_DIM + h * HD + cq + 4];
        uint4 hh, ll;
        split4(v0, hh, ll); *(uint4*)&Ah[r][cq] = hh;     *(uint4*)&Al[r][cq] = ll;
        split4(v1, hh, ll); *(uint4*)&Ah[r][cq + 4] = hh; *(uint4*)&Al[r][cq + 4] = ll;
        float4 w0 = *(const float4*)&Wkv[(size_t)(bnj + r) * 512 + h * HD + cq];
        float4 w1 = *(const float4*)&Wkv[(size_t)(bnj + r) * 512 + h * HD + cq + 4];
        split4(w0, hh, ll); *(uint4*)&Nh[r][cq] = hh;     *(uint4*)&Nl[r][cq] = ll;
        split4(w1, hh, ll); *(uint4*)&Nh[r][cq + 4] = hh; *(uint4*)&Nl[r][cq + 4] = ll;
    }
    __syncthreads();

    float c[2][2][4] = {};
#pragma unroll
    for (int ks = 0; ks < 4; ks++) {
        int k8 = ks * 8;
        uint32_t ah[2][4], al[2][4], bh[2][2], bl[2][2];
#pragma unroll
        for (int ma = 0; ma < 2; ma++) {
            int m0 = wm * 32 + ma * 16 + gid;
            ah[ma][0] = Ah[m0][k8 + tig];         al[ma][0] = Al[m0][k8 + tig];
            ah[ma][1] = Ah[m0 + 8][k8 + tig];     al[ma][1] = Al[m0 + 8][k8 + tig];
            ah[ma][2] = Ah[m0][k8 + tig + 4];     al[ma][2] = Al[m0][k8 + tig + 4];
            ah[ma][3] = Ah[m0 + 8][k8 + tig + 4]; al[ma][3] = Al[m0 + 8][k8 + tig + 4];
        }
#pragma unroll
        for (int na = 0; na < 2; na++) {
            int n0 = wn * 16 + na * 8 + gid;
            bh[na][0] = Nh[n0][k8 + tig];     bl[na][0] = Nl[n0][k8 + tig];
            bh[na][1] = Nh[n0][k8 + tig + 4]; bl[na][1] = Nl[n0][k8 + tig + 4];
        }
#pragma unroll
        for (int ma = 0; ma < 2; ma++)
#pragma unroll
            for (int na = 0; na < 2; na++)
                mma3(c[ma][na], ah[ma], al[ma], bh[na], bl[na]);
    }

#pragma unroll
    for (int ma = 0; ma < 2; ma++)
#pragma unroll
        for (int na = 0; na < 2; na++) {
            int srow = bm + wm * 32 + ma * 16 + gid;
            int col  = bnj + wn * 16 + na * 8 + 2 * tig;
            float2 o0; o0.x = c[ma][na][0]; o0.y = c[ma][na][1];
            float2 o1; o1.x = c[ma][na][2]; o1.y = c[ma][na][3];
            *(float2*)&g_qk[(size_t)srow * (NH * D_DIM) + h * D_DIM + col]       = o0;
            *(float2*)&g_qk[(size_t)(srow + 8) * (NH * D_DIM) + h * D_DIM + col] = o1;
        }

    if (blockIdx.y == 0 && t < 64) {
        int s = bm + t;
        float acc = 0.f;
#pragma unroll
        for (int d = 0; d < HD; d++)
            acc += g_q[(size_t)s * H_DIM + h * HD + d] * bkv[h * HD + d];
        g_qb[s * NH + h] = acc;
    }
}

// ---------- K4 tensor: pooled_h = Ahat_h[64x256] @ Wv_h[256x32] ---------
__global__ void __launch_bounds__(256)
k_pool_tf32(const float* __restrict__ Wkv, const float* __restrict__ bkv) {
    __shared__ uint32_t Ah[64][36], Al[64][36];
    __shared__ uint32_t Bh[32][40], Bl[32][40];
    int t = threadIdx.x;
    int lane = t & 31, w = t >> 5;
    int gid = lane >> 2, tig = lane & 3;
    int wm = w & 3, wn = w >> 2;
    int bm = blockIdx.x * 64, h = blockIdx.y;
    int arr = t >> 2, acq = (t & 3) * 8;
    int bkk = t >> 3, bn4 = (t & 7) * 4;

    const float* Abase = g_Ahat + (size_t)bm * (NH * D_DIM) + h * D_DIM;
    float c[2][4] = {};
    float4 ra0, ra1, rb;

    ra0 = *(const float4*)&Abase[(size_t)arr * (NH * D_DIM) + acq];
    ra1 = *(const float4*)&Abase[(size_t)arr * (NH * D_DIM) + acq + 4];
    rb  = *(const float4*)&Wkv[(size_t)bkk * 512 + 256 + h * HD + bn4];

    for (int ch = 0; ch < 8; ch++) {
        if (ch > 0) __syncthreads();
        {
            uint4 hh, ll;
            split4(ra0, hh, ll);
            *(uint4*)&Ah[arr][acq] = hh;     *(uint4*)&Al[arr][acq] = ll;
            split4(ra1, hh, ll);
            *(uint4*)&Ah[arr][acq + 4] = hh; *(uint4*)&Al[arr][acq + 4] = ll;
            split4(rb, hh, ll);
            *(uint4*)&Bh[bkk][bn4] = hh;     *(uint4*)&Bl[bkk][bn4] = ll;
        }
        __syncthreads();
        if (ch + 1 < 8) {
            int k0 = (ch + 1) * 32;
            ra0 = *(const float4*)&Abase[(size_t)arr * (NH * D_DIM) + k0 + acq];
            ra1 = *(const float4*)&Abase[(size_t)arr * (NH * D_DIM) + k0 + acq + 4];
            rb  = *(const float4*)&Wkv[(size_t)(k0 + bkk) * 512 + 256 + h * HD + bn4];
        }
#pragma unroll
        for (int ks = 0; ks < 4; ks++) {
            int k8 = ks * 8;
            uint32_t ah[4], al[4], bh[2][2], bl[2][2];
            int m0 = wm * 16 + gid;
            ah[0] = Ah[m0][k8 + tig];         al[0] = Al[m0][k8 + tig];
            ah[1] = Ah[m0 + 8][k8 + tig];     al[1] = Al[m0 + 8][k8 + tig];
            ah[2] = Ah[m0][k8 + tig + 4];     al[2] = Al[m0][k8 + tig + 4];
            ah[3] = Ah[m0 + 8][k8 + tig + 4]; al[3] = Al[m0 + 8][k8 + tig + 4];
#pragma unroll
            for (int na = 0; na < 2; na++) {
                int n0 = wn * 16 + na * 8 + gid;
                bh[na][0] = Bh[k8 + tig][n0];     bl[na][0] = Bl[k8 + tig][n0];
                bh[na][1] = Bh[k8 + tig + 4][n0]; bl[na][1] = Bl[k8 + tig + 4][n0];
            }
#pragma unroll
            for (int na = 0; na < 2; na++)
                mma3(c[na], ah, al, bh[na], bl[na]);
        }
    }

#pragma unroll
    for (int na = 0; na < 2; na++) {
        int row = bm + wm * 16 + gid;
        int col = wn * 16 + na * 8 + 2 * tig;
        float2 bv = *(const float2*)&bkv[256 + h * HD + col];
        bool ne0 = g_off[row + 1] > g_off[row];
        bool ne1 = g_off[row + 9] > g_off[row + 8];
        float2 o0, o1;
        o0.x = c[na][0] + (ne0 ? bv.x : 0.f); o0.y = c[na][1] + (ne0 ? bv.y : 0.f);
        o1.x = c[na][2] + (ne1 ? bv.x : 0.f); o1.y = c[na][3] + (ne1 ? bv.y : 0.f);
        *(float2*)&g_pooled[(size_t)row * H_DIM + h * HD + col]       = o0;
        *(float2*)&g_pooled[(size_t)(row + 8) * H_DIM + h * HD + col] = o1;
    }
}

// ---------------- K3: streaming softmax-pool accumulation ---------------
// One block per sample; 4 blocks/SM (~50KB smem). Data movement via ONE
// cp.async.bulk per tile (elements are consecutive -> 32KB contiguous) +
// mbarrier with expect_tx and parity-tracked waits. Replaces 2048 LDGSTS
// ops/tile (rt 8 cyc/op/SMSP) with a single bulk op. sE is unpadded
// (stride 256); the score phase rotates the float4 read order per lane
// (off = ((o8+lane)&7)*4) so every quarter-warp covers all 32 banks for
// both the E-row and qk reads. A-update scalar reads (bank = t mod 32)
// are conflict-free at stride 256. No running max (scores O(+-8), exp
// fp32-safe; max-shift cancels exactly in probs).
// Smem floats: sQK[0,2048) sE[2048,10240) sPart[10240,12336)
//              sP[12336,12720) sD[12720,12728) sQBs[12728,12736)
//              mbar (8B) at [12736,12738)
#define ATTN_SMEM_FLOATS 12744

__global__ void __launch_bounds__(256)
k_attn(const float* __restrict__ emb, float scale) {
    extern __shared__ float dyn[];
    float* sQK   = dyn;
    float* sE    = dyn + 2048;
    float* sPart = dyn + 10240;
    float* sP    = dyn + 12336;
    float* sD    = dyn + 12720;
    float* sQBs  = dyn + 12728;
    uint32_t smem_u32 = (uint32_t)__cvta_generic_to_shared(dyn);
    uint32_t mbar     = smem_u32 + 12736 * 4;
    uint32_t sQK_u32  = smem_u32;
    uint32_t sE_u32   = smem_u32 + 2048 * 4;

    int s = blockIdx.x;
    int t = threadIdx.x;
    int lane = t & 31, w = t >> 5;

    int start = g_off[s], end = g_off[s + 1];

    if (t == 0) MBAR_INIT(mbar, 1);
    __syncthreads();     // mbar visible before any bulk targets it

    if (start < end) {
        if (t == 0) {
            int T = min(32, end - start);
            uint32_t ebytes = (uint32_t)T * 1024u;
            MBAR_EXPECT_TX(mbar, 8192u + ebytes);
            bulk_g2s(sQK_u32, g_qk + (size_t)s * (NH * D_DIM), 8192u, mbar);
            bulk_g2s(sE_u32, emb + (size_t)start * D_DIM, ebytes, mbar);
        }
        if (t < NH) sQBs[t] = g_qb[s * NH + t];
    }

    float a[NH];
#pragma unroll
    for (int i = 0; i < NH; i++) a[i] = 0.f;
    float d_w = 0.f;
    int j0 = w * 32;
    uint32_t phase = 0;

    for (int t0 = start; t0 < end; t0 += 32) {
        int T = min(32, end - t0);

        mbar_wait(mbar, phase);
        phase ^= 1;

        // ---- score partials: warp w covers j in [j0, j0+32), lane = element.
        //      Per-lane rotated float4 order keeps both loads conflict-free.
        {
            float acc[NH];
#pragma unroll
            for (int h = 0; h < NH; h++) acc[h] = 0.f;
#pragma unroll
            for (int o8 = 0; o8 < 8; o8++) {
                int off = ((o8 + lane) & 7) * 4;
                float4 ev = *(float4*)&sE[lane * 256 + j0 + off];
#pragma unroll
                for (int h = 0; h < NH; h++) {
                    float4 qv = *(float4*)&sQK[h * 256 + j0 + off];
                    acc[h] += ev.x * qv.x + ev.y * qv.y + ev.z * qv.z + ev.w * qv.w;
                }
            }
#pragma unroll
            for (int h = 0; h < NH; h++)
                sPart[lane * 65 + h * 8 + w] = acc[h];
        }
        __syncthreads();

        // ---- reduce partials + exp (no max shift): thread (lane=e, w=h)
        float p = 0.f;
        if (lane < T) {
            float sum = 0.f;
#pragma unroll
            for (int i = 0; i < 8; i++) sum += sPart[lane * 65 + w * 8 + i];
            p = __expf(scale * (sum + sQBs[w]));
        }
        sP[lane * 12 + w] = p;
        float ps = p;
#pragma unroll
        for (int o = 16; o; o >>= 1) ps += __shfl_xor_sync(0xffffffffu, ps, o);
        d_w += ps;
        __syncthreads();

        // ---- A update: thread owns column j = t for all 8 heads
        for (int e = 0; e < T; e++) {
            float4 p0 = *(float4*)&sP[e * 12 + 0];
            float4 p1 = *(float4*)&sP[e * 12 + 4];
            float ev = sE[e * 256 + t];
            a[0] += p0.x * ev; a[1] += p0.y * ev; a[2] += p0.z * ev; a[3] += p0.w * ev;
            a[4] += p1.x * ev; a[5] += p1.y * ev; a[6] += p1.z * ev; a[7] += p1.w * ev;
        }
        __syncthreads();   // all sE reads done; safe to overwrite via bulk

        if (t == 0 && t0 + 32 < end) {
            int Tn = min(32, end - (t0 + 32));
            MBAR_EXPECT_TX(mbar, (uint32_t)Tn * 1024u);
            bulk_g2s(sE_u32, emb + (size_t)(t0 + 32) * D_DIM,
                     (uint32_t)Tn * 1024u, mbar);
        }
    }

    if (lane == 0) sD[w] = d_w;
    __syncthreads();
    float* outp = g_Ahat + (size_t)s * (NH * D_DIM);
#pragma unroll
    for (int h = 0; h < NH; h++) {
        float dh = sD[h];
        outp[h * D_DIM + t] = (dh > 0.f) ? (a[h] / dh) : 0.f;
    }
}

// ---------------- launch ----------------
extern "C" void kernel_launch(void* const* d_in, const int* in_sizes, int n_in,
                              void* d_out, int out_size) {
    const float* queries = (const float*)d_in[0];
    const float* emb     = (const float*)d_in[1];
    const int*   map     = (const int*)  d_in[2];
    // num_samples may or may not be materialized as a device input
    int base = (n_in >= 10 && in_sizes[3] < 16) ? 4 : 3;
    const float* Wq  = (const float*)d_in[base + 0];
    const float* bq  = (const float*)d_in[base + 1];
    const float* Wkv = (const float*)d_in[base + 2];
    const float* bkv = (const float*)d_in[base + 3];
    const float* Wo  = (const float*)d_in[base + 4];
    const float* bo  = (const float*)d_in[base + 5];
    float* out = (float*)d_out;

    int S = in_sizes[0] / D_DIM;     // 4096
    int N = in_sizes[1] / D_DIM;     // 262144
    float scale = 0.17677669529663687f;   // 1/sqrt(32)

    float* dq      = nullptr; cudaGetSymbolAddress((void**)&dq,      g_q);
    float* dpooled = nullptr; cudaGetSymbolAddress((void**)&dpooled, g_pooled);

    cudaFuncSetAttribute(k_attn, cudaFuncAttributeMaxDynamicSharedMemorySize,
                         ATTN_SMEM_FLOATS * 4);

    // K0: segment offsets
    k_offsets<<<(S + 1 + 255) / 256, 256>>>(map, N, S);
    // K1: q projection (tensor core, 3xTF32)
    {
        dim3 grid(S / 64, H_DIM / 64);
        k_gemm_tf32<<<grid, 256>>>(queries, Wq, bq, dq, S, D_DIM, H_DIM);
    }
    // K2: qk/qb precompute (tensor core)
    {
        dim3 grid(S / 64, D_DIM / 64, NH);
        k_qk_tf32<<<grid, 256>>>(Wkv, bkv);
    }
    // K3: streaming attention accumulation (cp.async.bulk + mbarrier)
    k_attn<<<S, 256, ATTN_SMEM_FLOATS * 4>>>(emb, scale);
    // K4: pooled projection through Wv (tensor core)
    {
        dim3 grid(S / 64, NH);
        k_pool_tf32<<<grid, 256>>>(Wkv, bkv);
    }
    // K5: output projection (tensor core, 3xTF32)
    {
        dim3 grid(S / 64, H_DIM / 64);
        k_gemm_tf32<<<grid, 256>>>(dpooled, Wo, bo, out, S, H_DIM, H_DIM);
    }
}

// round 10
// speedup vs baseline: 1.0677x; 1.0677x over previous
#include <cuda_runtime.h>
#include <cstdint>
#include <cstddef>

// Problem constants (fixed shapes for this problem)
#define S_MAX   4096
#define D_DIM   256
#define NH      8
#define HD      32
#define H_DIM   256

// ---------------- device scratch (no cudaMalloc allowed) ----------------
__device__ float g_q[S_MAX * H_DIM];              // q = queries@Wq + bq
__device__ float g_qk[S_MAX * NH * D_DIM];        // qk[s][h][j]
__device__ float g_qb[S_MAX * NH];                // qb[s][h]
__device__ float g_Ahat[S_MAX * NH * D_DIM];      // A/denom
__device__ float g_pooled[S_MAX * H_DIM];
__device__ int   g_off[S_MAX + 1];

// ---------------- cp.async helpers ----------------
__device__ __forceinline__ void cpa16(float* dst, const float* src) {
    uint32_t d = (uint32_t)__cvta_generic_to_shared(dst);
    asm volatile("cp.async.cg.shared.global [%0], [%1], 16;" :: "r"(d), "l"(src));
}
#define CPA_COMMIT() asm volatile("cp.async.commit_group;")
#define CPA_WAIT0()  asm volatile("cp.async.wait_group 0;")

// ---------------- tf32 3x-split helpers ----------------
__device__ __forceinline__ void tf32_split(float x, uint32_t& hi, uint32_t& lo) {
    asm("cvt.rna.tf32.f32 %0, %1;" : "=r"(hi) : "f"(x));
    float r = x - __uint_as_float(hi);
    asm("cvt.rna.tf32.f32 %0, %1;" : "=r"(lo) : "f"(r));
}
__device__ __forceinline__ void split4(float4 v, uint4& h, uint4& l) {
    tf32_split(v.x, h.x, l.x); tf32_split(v.y, h.y, l.y);
    tf32_split(v.z, h.z, l.z); tf32_split(v.w, h.w, l.w);
}
__device__ __forceinline__ void mma_tf32(float* c, const uint32_t* a, const uint32_t* b) {
    asm("mma.sync.aligned.m16n8k8.row.col.f32.tf32.tf32.f32 "
        "{%0,%1,%2,%3}, {%4,%5,%6,%7}, {%8,%9}, {%0,%1,%2,%3};"
        : "+f"(c[0]), "+f"(c[1]), "+f"(c[2]), "+f"(c[3])
        : "r"(a[0]), "r"(a[1]), "r"(a[2]), "r"(a[3]),
          "r"(b[0]), "r"(b[1]));
}
__device__ __forceinline__ void mma3(float* c, const uint32_t* ah, const uint32_t* al,
                                     const uint32_t* bh, const uint32_t* bl) {
    mma_tf32(c, ah, bh);
    mma_tf32(c, ah, bl);
    mma_tf32(c, al, bh);
}

// ---------------- K0: segment offsets via binary search (idx sorted) ----
__global__ void k_offsets(const int* __restrict__ map, int N, int S) {
    int s = blockIdx.x * blockDim.x + threadIdx.x;
    if (s > S) return;
    int lo = 0, hi = N;
    while (lo < hi) {
        int mid = (lo + hi) >> 1;
        if (map[mid] < s) lo = mid + 1; else hi = mid;
    }
    g_off[s] = lo;
}

// ---------- tensor GEMM (3xTF32, pre-split smem): C = A@B + bias --------
__global__ void __launch_bounds__(256)
k_gemm_tf32(const float* __restrict__ A, const float* __restrict__ B,
            const float* __restrict__ bias, float* __restrict__ C,
            int M, int K, int N) {
    __shared__ uint32_t Ah[64][36], Al[64][36];   // m-major: bank 4*gid+tig
    __shared__ uint32_t Bh[32][72], Bl[32][72];   // k-major: bank 8*tig+gid
    int t = threadIdx.x;
    int lane = t & 31, w = t >> 5;
    int gid = lane >> 2, tig = lane & 3;
    int wm = w & 1, wn = w >> 1;
    int bm = blockIdx.x * 64, bn = blockIdx.y * 64;
    int ar = t >> 2, ac = (t & 3) * 8;
    int br = t >> 3, bc = (t & 7) * 8;

    float c[2][2][4] = {};
    float4 ra0, ra1, rb0, rb1;

    ra0 = *(const float4*)&A[(size_t)(bm + ar) * K + ac];
    ra1 = *(const float4*)&A[(size_t)(bm + ar) * K + ac + 4];
    rb0 = *(const float4*)&B[(size_t)br * N + bn + bc];
    rb1 = *(const float4*)&B[(size_t)br * N + bn + bc + 4];

    int nc = K / 32;
    for (int ch = 0; ch < nc; ch++) {
        if (ch > 0) __syncthreads();
        {
            uint4 h, l;
            split4(ra0, h, l);
            *(uint4*)&Ah[ar][ac] = h;     *(uint4*)&Al[ar][ac] = l;
            split4(ra1, h, l);
            *(uint4*)&Ah[ar][ac + 4] = h; *(uint4*)&Al[ar][ac + 4] = l;
            split4(rb0, h, l);
            *(uint4*)&Bh[br][bc] = h;     *(uint4*)&Bl[br][bc] = l;
            split4(rb1, h, l);
            *(uint4*)&Bh[br][bc + 4] = h; *(uint4*)&Bl[br][bc + 4] = l;
        }
        __syncthreads();
        if (ch + 1 < nc) {
            int k0 = (ch + 1) * 32;
            ra0 = *(const float4*)&A[(size_t)(bm + ar) * K + k0 + ac];
            ra1 = *(const float4*)&A[(size_t)(bm + ar) * K + k0 + ac + 4];
            rb0 = *(const float4*)&B[(size_t)(k0 + br) * N + bn + bc];
            rb1 = *(const float4*)&B[(size_t)(k0 + br) * N + bn + bc + 4];
        }
#pragma unroll
        for (int ks = 0; ks < 4; ks++) {
            int k8 = ks * 8;
            uint32_t ah[2][4], al[2][4], bh[2][2], bl[2][2];
#pragma unroll
            for (int ma = 0; ma < 2; ma++) {
                int m0 = wm * 32 + ma * 16 + gid;
                ah[ma][0] = Ah[m0][k8 + tig];     al[ma][0] = Al[m0][k8 + tig];
                ah[ma][1] = Ah[m0 + 8][k8 + tig]; al[ma][1] = Al[m0 + 8][k8 + tig];
                ah[ma][2] = Ah[m0][k8 + tig + 4]; al[ma][2] = Al[m0][k8 + tig + 4];
                ah[ma][3] = Ah[m0 + 8][k8 + tig + 4]; al[ma][3] = Al[m0 + 8][k8 + tig + 4];
            }
#pragma unroll
            for (int na = 0; na < 2; na++) {
                int n0 = wn * 16 + na * 8 + gid;
                bh[na][0] = Bh[k8 + tig][n0];     bl[na][0] = Bl[k8 + tig][n0];
                bh[na][1] = Bh[k8 + tig + 4][n0]; bl[na][1] = Bl[k8 + tig + 4][n0];
            }
#pragma unroll
            for (int ma = 0; ma < 2; ma++)
#pragma unroll
                for (int na = 0; na < 2; na++)
                    mma3(c[ma][na], ah[ma], al[ma], bh[na], bl[na]);
        }
    }

#pragma unroll
    for (int ma = 0; ma < 2; ma++)
#pragma unroll
        for (int na = 0; na < 2; na++) {
            int row = bm + wm * 32 + ma * 16 + gid;
            int col = bn + wn * 16 + na * 8 + 2 * tig;
            float2 bv = *(const float2*)&bias[col];
            float2 o0; o0.x = c[ma][na][0] + bv.x; o0.y = c[ma][na][1] + bv.y;
            float2 o1; o1.x = c[ma][na][2] + bv.x; o1.y = c[ma][na][3] + bv.y;
            *(float2*)&C[(size_t)row * N + col]       = o0;
            *(float2*)&C[(size_t)(row + 8) * N + col] = o1;
        }
}

// ---------- K2 tensor: qk[s][h][j] = Q_h[s,:] . Wk_h[j,:]  (K=32) -------
__global__ void __launch_bounds__(256)
k_qk_tf32(const float* __restrict__ Wkv, const float* __restrict__ bkv) {
    __shared__ uint32_t Ah[64][36], Al[64][36];   // q slice  [s][d]
    __shared__ uint32_t Nh[64][36], Nl[64][36];   // Wk slice [j][d]
    int t = threadIdx.x;
    int lane = t & 31, w = t >> 5;
    int gid = lane >> 2, tig = lane & 3;
    int wm = w & 1, wn = w >> 1;
    int bm = blockIdx.x * 64, bnj = blockIdx.y * 64, h = blockIdx.z;
    int r = t >> 2, cq = (t & 3) * 8;

    {
        float4 v0 = *(const float4*)&g_q[(size_t)(bm + r) * H_DIM + h * HD + cq];
        float4 v1 = *(const float4*)&g_q[(size_t)(bm + r) * H_DIM + h * HD + cq + 4];
        uint4 hh, ll;
        split4(v0, hh, ll); *(uint4*)&Ah[r][cq] = hh;     *(uint4*)&Al[r][cq] = ll;
        split4(v1, hh, ll); *(uint4*)&Ah[r][cq + 4] = hh; *(uint4*)&Al[r][cq + 4] = ll;
        float4 w0 = *(const float4*)&Wkv[(size_t)(bnj + r) * 512 + h * HD + cq];
        float4 w1 = *(const float4*)&Wkv[(size_t)(bnj + r) * 512 + h * HD + cq + 4];
        split4(w0, hh, ll); *(uint4*)&Nh[r][cq] = hh;     *(uint4*)&Nl[r][cq] = ll;
        split4(w1, hh, ll); *(uint4*)&Nh[r][cq + 4] = hh; *(uint4*)&Nl[r][cq + 4] = ll;
    }
    __syncthreads();

    float c[2][2][4] = {};
#pragma unroll
    for (int ks = 0; ks < 4; ks++) {
        int k8 = ks * 8;
        uint32_t ah[2][4], al[2][4], bh[2][2], bl[2][2];
#pragma unroll
        for (int ma = 0; ma < 2; ma++) {
            int m0 = wm * 32 + ma * 16 + gid;
            ah[ma][0] = Ah[m0][k8 + tig];         al[ma][0] = Al[m0][k8 + tig];
            ah[ma][1] = Ah[m0 + 8][k8 + tig];     al[ma][1] = Al[m0 + 8][k8 + tig];
            ah[ma][2] = Ah[m0][k8 + tig + 4];     al[ma][2] = Al[m0][k8 + tig + 4];
            ah[ma][3] = Ah[m0 + 8][k8 + tig + 4]; al[ma][3] = Al[m0 + 8][k8 + tig + 4];
        }
#pragma unroll
        for (int na = 0; na < 2; na++) {
            int n0 = wn * 16 + na * 8 + gid;
            bh[na][0] = Nh[n0][k8 + tig];     bl[na][0] = Nl[n0][k8 + tig];
            bh[na][1] = Nh[n0][k8 + tig + 4]; bl[na][1] = Nl[n0][k8 + tig + 4];
        }
#pragma unroll
        for (int ma = 0; ma < 2; ma++)
#pragma unroll
            for (int na = 0; na < 2; na++)
                mma3(c[ma][na], ah[ma], al[ma], bh[na], bl[na]);
    }

#pragma unroll
    for (int ma = 0; ma < 2; ma++)
#pragma unroll
        for (int na = 0; na < 2; na++) {
            int srow = bm + wm * 32 + ma * 16 + gid;
            int col  = bnj + wn * 16 + na * 8 + 2 * tig;
            float2 o0; o0.x = c[ma][na][0]; o0.y = c[ma][na][1];
            float2 o1; o1.x = c[ma][na][2]; o1.y = c[ma][na][3];
            *(float2*)&g_qk[(size_t)srow * (NH * D_DIM) + h * D_DIM + col]       = o0;
            *(float2*)&g_qk[(size_t)(srow + 8) * (NH * D_DIM) + h * D_DIM + col] = o1;
        }

    if (blockIdx.y == 0 && t < 64) {
        int s = bm + t;
        float acc = 0.f;
#pragma unroll
        for (int d = 0; d < HD; d++)
            acc += g_q[(size_t)s * H_DIM + h * HD + d] * bkv[h * HD + d];
        g_qb[s * NH + h] = acc;
    }
}

// ---------- K4 tensor: pooled_h = Ahat_h[64x256] @ Wv_h[256x32] ---------
__global__ void __launch_bounds__(256)
k_pool_tf32(const float* __restrict__ Wkv, const float* __restrict__ bkv) {
    __shared__ uint32_t Ah[64][36], Al[64][36];
    __shared__ uint32_t Bh[32][40], Bl[32][40];
    int t = threadIdx.x;
    int lane = t & 31, w = t >> 5;
    int gid = lane >> 2, tig = lane & 3;
    int wm = w & 3, wn = w >> 2;
    int bm = blockIdx.x * 64, h = blockIdx.y;
    int arr = t >> 2, acq = (t & 3) * 8;
    int bkk = t >> 3, bn4 = (t & 7) * 4;

    const float* Abase = g_Ahat + (size_t)bm * (NH * D_DIM) + h * D_DIM;
    float c[2][4] = {};
    float4 ra0, ra1, rb;

    ra0 = *(const float4*)&Abase[(size_t)arr * (NH * D_DIM) + acq];
    ra1 = *(const float4*)&Abase[(size_t)arr * (NH * D_DIM) + acq + 4];
    rb  = *(const float4*)&Wkv[(size_t)bkk * 512 + 256 + h * HD + bn4];

    for (int ch = 0; ch < 8; ch++) {
        if (ch > 0) __syncthreads();
        {
            uint4 hh, ll;
            split4(ra0, hh, ll);
            *(uint4*)&Ah[arr][acq] = hh;     *(uint4*)&Al[arr][acq] = ll;
            split4(ra1, hh, ll);
            *(uint4*)&Ah[arr][acq + 4] = hh; *(uint4*)&Al[arr][acq + 4] = ll;
            split4(rb, hh, ll);
            *(uint4*)&Bh[bkk][bn4] = hh;     *(uint4*)&Bl[bkk][bn4] = ll;
        }
        __syncthreads();
        if (ch + 1 < 8) {
            int k0 = (ch + 1) * 32;
            ra0 = *(const float4*)&Abase[(size_t)arr * (NH * D_DIM) + k0 + acq];
            ra1 = *(const float4*)&Abase[(size_t)arr * (NH * D_DIM) + k0 + acq + 4];
            rb  = *(const float4*)&Wkv[(size_t)(k0 + bkk) * 512 + 256 + h * HD + bn4];
        }
#pragma unroll
        for (int ks = 0; ks < 4; ks++) {
            int k8 = ks * 8;
            uint32_t ah[4], al[4], bh[2][2], bl[2][2];
            int m0 = wm * 16 + gid;
            ah[0] = Ah[m0][k8 + tig];         al[0] = Al[m0][k8 + tig];
            ah[1] = Ah[m0 + 8][k8 + tig];     al[1] = Al[m0 + 8][k8 + tig];
            ah[2] = Ah[m0][k8 + tig + 4];     al[2] = Al[m0][k8 + tig + 4];
            ah[3] = Ah[m0 + 8][k8 + tig + 4]; al[3] = Al[m0 + 8][k8 + tig + 4];
#pragma unroll
            for (int na = 0; na < 2; na++) {
                int n0 = wn * 16 + na * 8 + gid;
                bh[na][0] = Bh[k8 + tig][n0];     bl[na][0] = Bl[k8 + tig][n0];
                bh[na][1] = Bh[k8 + tig + 4][n0]; bl[na][1] = Bl[k8 + tig + 4][n0];
            }
#pragma unroll
            for (int na = 0; na < 2; na++)
                mma3(c[na], ah, al, bh[na], bl[na]);
        }
    }

#pragma unroll
    for (int na = 0; na < 2; na++) {
        int row = bm + wm * 16 + gid;
        int col = wn * 16 + na * 8 + 2 * tig;
        float2 bv = *(const float2*)&bkv[256 + h * HD + col];
        bool ne0 = g_off[row + 1] > g_off[row];
        bool ne1 = g_off[row + 9] > g_off[row + 8];
        float2 o0, o1;
        o0.x = c[na][0] + (ne0 ? bv.x : 0.f); o0.y = c[na][1] + (ne0 ? bv.y : 0.f);
        o1.x = c[na][2] + (ne1 ? bv.x : 0.f); o1.y = c[na][3] + (ne1 ? bv.y : 0.f);
        *(float2*)&g_pooled[(size_t)row * H_DIM + h * HD + col]       = o0;
        *(float2*)&g_pooled[(size_t)(row + 8) * H_DIM + h * HD + col] = o1;
    }
}

// ---------------- K3: streaming softmax-pool accumulation ---------------
// One block per sample; 4 blocks/SM (51.6KB smem, <=64 regs). cp.async
// per-16B loads (R8-proven). Score phase as R6/R8. A-update TENSORIZED:
// A[j,h] += sum_e E[e,j]*P[e,h] as mma.m16n8k8 with M=j(16), N=heads(8),
// K=elems(8); warp w owns j in [32w,32w+32) via 2 M-atoms, accumulators
// live in 8 regs/thread across all tiles; no cross-warp reduce needed.
// 3xTF32 split keeps ~2^-22 accuracy. Partial tiles: sE rows [T,32)
// zero-filled so P=0 rows can't inject NaN via 0*garbage.
// Smem floats: sQK[0,2080) sE[2080,10400) sPart[10400,12496)
//              sP[12496,12880) sD[12880,12888) sQBs[12888,12896)
#define ATTN_SMEM_FLOATS (12896)
#define SE_STRIDE 260

__global__ void __launch_bounds__(256, 4)
k_attn(const float* __restrict__ emb, float scale) {
    extern __shared__ float dyn[];
    float* sQK   = dyn;
    float* sE    = dyn + 2080;
    float* sPart = dyn + 10400;
    float* sP    = dyn + 12496;
    float* sD    = dyn + 12880;
    float* sQBs  = dyn + 12888;

    int s = blockIdx.x;
    int t = threadIdx.x;
    int lane = t & 31, w = t >> 5;
    int gid = lane >> 2, tig = lane & 3;

    int start = g_off[s], end = g_off[s + 1];

    // prefetch first emb tile (overlaps qk load)
    if (start < end) {
        int T = min(32, end - start);
        for (int i = t; i < T * 64; i += 256) {
            int e = i >> 6, j4 = (i & 63) * 4;
            cpa16(&sE[e * SE_STRIDE + j4],
                  emb + (size_t)(start + e) * D_DIM + j4);
        }
    }
    CPA_COMMIT();

    const float* qkp = g_qk + (size_t)s * (NH * D_DIM);
    for (int i = t; i < (NH * D_DIM) / 4; i += 256) {
        float4 v = *(const float4*)(qkp + i * 4);
        int h = i >> 6, j = (i * 4) & 255;
        *(float4*)&sQK[h * SE_STRIDE + j] = v;
    }
    if (t < NH) sQBs[t] = g_qb[s * NH + t];

    // A accumulators: c[ma][0..3] = A at (j = 32w + 16ma + gid (+8), h = 2tig (+1))
    float c[2][4] = {};
    float d_w = 0.f;
    int j0 = w * 32;
    __syncthreads();   // sQK ready

    for (int t0 = start; t0 < end; t0 += 32) {
        int T = min(32, end - t0);

        CPA_WAIT0();
        __syncthreads();   // sE full

        if (T < 32) {      // zero tail rows so 0*garbage can't make NaN in mma
            for (int i = t; i < (32 - T) * 64; i += 256) {
                int e = T + (i >> 6), j4 = (i & 63) * 4;
                *(float4*)&sE[e * SE_STRIDE + j4] = make_float4(0.f, 0.f, 0.f, 0.f);
            }
            __syncthreads();   // T uniform across block
        }

        // ---- score partials: warp w covers j in [j0, j0+32), lane = element
        {
            float acc[NH];
#pragma unroll
            for (int h = 0; h < NH; h++) acc[h] = 0.f;
#pragma unroll
            for (int half = 0; half < 2; half++) {
                float4 er[4];
#pragma unroll
                for (int q = 0; q < 4; q++)
                    er[q] = *(float4*)&sE[lane * SE_STRIDE + j0 + half * 16 + q * 4];
#pragma unroll
                for (int h = 0; h < NH; h++) {
#pragma unroll
                    for (int q = 0; q < 4; q++) {
                        float4 qv = *(float4*)&sQK[h * SE_STRIDE + j0 + half * 16 + q * 4];
                        acc[h] += er[q].x * qv.x + er[q].y * qv.y
                                + er[q].z * qv.z + er[q].w * qv.w;
                    }
                }
            }
#pragma unroll
            for (int h = 0; h < NH; h++)
                sPart[lane * 65 + h * 8 + w] = acc[h];
        }
        __syncthreads();

        // ---- reduce partials + exp (no max shift): thread (lane=e, w=h)
        float p = 0.f;
        if (lane < T) {
            float sum = 0.f;
#pragma unroll
            for (int i = 0; i < 8; i++) sum += sPart[lane * 65 + w * 8 + i];
            p = __expf(scale * (sum + sQBs[w]));
        }
        sP[lane * 12 + w] = p;
        float ps = p;
#pragma unroll
        for (int o = 16; o; o >>= 1) ps += __shfl_xor_sync(0xffffffffu, ps, o);
        d_w += ps;
        __syncthreads();

        // ---- A update via tensor cores: D[16j x 8h] += E^T-frag @ P-frag
#pragma unroll
        for (int ks = 0; ks < 4; ks++) {
            int e0 = 8 * ks + tig;
            uint32_t bh[2], bl[2];
            tf32_split(sP[e0 * 12 + gid],       bh[0], bl[0]);
            tf32_split(sP[(e0 + 4) * 12 + gid], bh[1], bl[1]);
#pragma unroll
            for (int ma = 0; ma < 2; ma++) {
                int jb = j0 + ma * 16 + gid;
                uint32_t ah[4], al[4];
                tf32_split(sE[e0 * SE_STRIDE + jb],           ah[0], al[0]);
                tf32_split(sE[e0 * SE_STRIDE + jb + 8],       ah[1], al[1]);
                tf32_split(sE[(e0 + 4) * SE_STRIDE + jb],     ah[2], al[2]);
                tf32_split(sE[(e0 + 4) * SE_STRIDE + jb + 8], ah[3], al[3]);
                mma3(c[ma], ah, al, bh, bl);
            }
        }
        __syncthreads();   // all sE reads done; safe to refill

        // issue next tile's loads
        if (t0 + 32 < end) {
            int Tn = min(32, end - (t0 + 32));
            for (int i = t; i < Tn * 64; i += 256) {
                int e = i >> 6, j4 = (i & 63) * 4;
                cpa16(&sE[e * SE_STRIDE + j4],
                      emb + (size_t)(t0 + 32 + e) * D_DIM + j4);
            }
        }
        CPA_COMMIT();
    }

    if (lane == 0) sD[w] = d_w;
    __syncthreads();

    // epilogue: c[ma] holds (j = j0 + 16ma + gid (+8), h = 2tig (+1))
    {
        float dh0 = sD[2 * tig],     rdh0 = (dh0 > 0.f) ? (1.0f / dh0) : 0.f;
        float dh1 = sD[2 * tig + 1], rdh1 = (dh1 > 0.f) ? (1.0f / dh1) : 0.f;
        float* outp = g_Ahat + (size_t)s * (NH * D_DIM);
#pragma unroll
        for (int ma = 0; ma < 2; ma++) {
            int j = j0 + ma * 16 + gid;
            outp[(2 * tig) * D_DIM + j]         = c[ma][0] * rdh0;
            outp[(2 * tig + 1) * D_DIM + j]     = c[ma][1] * rdh1;
            outp[(2 * tig) * D_DIM + j + 8]     = c[ma][2] * rdh0;
            outp[(2 * tig + 1) * D_DIM + j + 8] = c[ma][3] * rdh1;
        }
    }
}

// ---------------- launch ----------------
extern "C" void kernel_launch(void* const* d_in, const int* in_sizes, int n_in,
                              void* d_out, int out_size) {
    const float* queries = (const float*)d_in[0];
    const float* emb     = (const float*)d_in[1];
    const int*   map     = (const int*)  d_in[2];
    // num_samples may or may not be materialized as a device input
    int base = (n_in >= 10 && in_sizes[3] < 16) ? 4 : 3;
    const float* Wq  = (const float*)d_in[base + 0];
    const float* bq  = (const float*)d_in[base + 1];
    const float* Wkv = (const float*)d_in[base + 2];
    const float* bkv = (const float*)d_in[base + 3];
    const float* Wo  = (const float*)d_in[base + 4];
    const float* bo  = (const float*)d_in[base + 5];
    float* out = (float*)d_out;

    int S = in_sizes[0] / D_DIM;     // 4096
    int N = in_sizes[1] / D_DIM;     // 262144
    float scale = 0.17677669529663687f;   // 1/sqrt(32)

    float* dq      = nullptr; cudaGetSymbolAddress((void**)&dq,      g_q);
    float* dpooled = nullptr; cudaGetSymbolAddress((void**)&dpooled, g_pooled);

    cudaFuncSetAttribute(k_attn, cudaFuncAttributeMaxDynamicSharedMemorySize,
                         ATTN_SMEM_FLOATS * 4);

    // K0: segment offsets
    k_offsets<<<(S + 1 + 255) / 256, 256>>>(map, N, S);
    // K1: q projection (tensor core, 3xTF32)
    {
        dim3 grid(S / 64, H_DIM / 64);
        k_gemm_tf32<<<grid, 256>>>(queries, Wq, bq, dq, S, D_DIM, H_DIM);
    }
    // K2: qk/qb precompute (tensor core)
    {
        dim3 grid(S / 64, D_DIM / 64, NH);
        k_qk_tf32<<<grid, 256>>>(Wkv, bkv);
    }
    // K3: streaming attention accumulation (tensorized A-update)
    k_attn<<<S, 256, ATTN_SMEM_FLOATS * 4>>>(emb, scale);
    // K4: pooled projection through Wv (tensor core)
    {
        dim3 grid(S / 64, NH);
        k_pool_tf32<<<grid, 256>>>(Wkv, bkv);
    }
    // K5: output projection (tensor core, 3xTF32)
    {
        dim3 grid(S / 64, H_DIM / 64);
        k_gemm_tf32<<<grid, 256>>>(dpooled, Wo, bo, out, S, H_DIM, H_DIM);
    }
}

// round 11
// speedup vs baseline: 1.2880x; 1.2064x over previous
#include <cuda_runtime.h>
#include <cstdint>
#include <cstddef>

// Problem constants (fixed shapes for this problem)
#define S_MAX   4096
#define D_DIM   256
#define NH      8
#define HD      32
#define H_DIM   256

// ---------------- device scratch (no cudaMalloc allowed) ----------------
__device__ float g_q[S_MAX * H_DIM];              // q = queries@Wq + bq
__device__ float g_qk[S_MAX * NH * D_DIM];        // qk[s][h][j]
__device__ float g_qb[S_MAX * NH];                // qb[s][h]
__device__ float g_Ahat[S_MAX * NH * D_DIM];      // A/denom
__device__ float g_pooled[S_MAX * H_DIM];
__device__ int   g_off[S_MAX + 1];

// ---------------- cp.async helpers ----------------
__device__ __forceinline__ void cpa16(float* dst, const float* src) {
    uint32_t d = (uint32_t)__cvta_generic_to_shared(dst);
    asm volatile("cp.async.cg.shared.global [%0], [%1], 16;" :: "r"(d), "l"(src));
}
#define CPA_COMMIT() asm volatile("cp.async.commit_group;")
#define CPA_WAIT0()  asm volatile("cp.async.wait_group 0;")

// ---------------- tf32 3x-split helpers (mask-split: 2 ops) -------------
// tf32 mma reads the top 19 bits of the f32 register; hi = masked x is
// exact, lo = x - hi holds the remaining 13 mantissa bits (its own tf32
// truncation is ~2^-21 relative). 3-term product keeps ~2^-21 accuracy.
__device__ __forceinline__ void tf32_split(float x, uint32_t& hi, uint32_t& lo) {
    hi = __float_as_uint(x) & 0xFFFFE000u;
    lo = __float_as_uint(x - __uint_as_float(hi));
}
__device__ __forceinline__ void split4(float4 v, uint4& h, uint4& l) {
    tf32_split(v.x, h.x, l.x); tf32_split(v.y, h.y, l.y);
    tf32_split(v.z, h.z, l.z); tf32_split(v.w, h.w, l.w);
}
__device__ __forceinline__ void mma_tf32(float* c, const uint32_t* a, const uint32_t* b) {
    asm("mma.sync.aligned.m16n8k8.row.col.f32.tf32.tf32.f32 "
        "{%0,%1,%2,%3}, {%4,%5,%6,%7}, {%8,%9}, {%0,%1,%2,%3};"
        : "+f"(c[0]), "+f"(c[1]), "+f"(c[2]), "+f"(c[3])
        : "r"(a[0]), "r"(a[1]), "r"(a[2]), "r"(a[3]),
          "r"(b[0]), "r"(b[1]));
}
__device__ __forceinline__ void mma3(float* c, const uint32_t* ah, const uint32_t* al,
                                     const uint32_t* bh, const uint32_t* bl) {
    mma_tf32(c, ah, bh);
    mma_tf32(c, ah, bl);
    mma_tf32(c, al, bh);
}

// ---------------- K0: segment offsets via binary search (idx sorted) ----
__global__ void k_offsets(const int* __restrict__ map, int N, int S) {
    int s = blockIdx.x * blockDim.x + threadIdx.x;
    if (s > S) return;
    int lo = 0, hi = N;
    while (lo < hi) {
        int mid = (lo + hi) >> 1;
        if (map[mid] < s) lo = mid + 1; else hi = mid;
    }
    g_off[s] = lo;
}

// ---------- tensor GEMM (3xTF32, pre-split smem): C = A@B + bias --------
__global__ void __launch_bounds__(256)
k_gemm_tf32(const float* __restrict__ A, const float* __restrict__ B,
            const float* __restrict__ bias, float* __restrict__ C,
            int M, int K, int N) {
    __shared__ uint32_t Ah[64][36], Al[64][36];   // m-major: bank 4*gid+tig
    __shared__ uint32_t Bh[32][72], Bl[32][72];   // k-major: bank 8*tig+gid
    int t = threadIdx.x;
    int lane = t & 31, w = t >> 5;
    int gid = lane >> 2, tig = lane & 3;
    int wm = w & 1, wn = w >> 1;
    int bm = blockIdx.x * 64, bn = blockIdx.y * 64;
    int ar = t >> 2, ac = (t & 3) * 8;
    int br = t >> 3, bc = (t & 7) * 8;

    float c[2][2][4] = {};
    float4 ra0, ra1, rb0, rb1;

    ra0 = *(const float4*)&A[(size_t)(bm + ar) * K + ac];
    ra1 = *(const float4*)&A[(size_t)(bm + ar) * K + ac + 4];
    rb0 = *(const float4*)&B[(size_t)br * N + bn + bc];
    rb1 = *(const float4*)&B[(size_t)br * N + bn + bc + 4];

    int nc = K / 32;
    for (int ch = 0; ch < nc; ch++) {
        if (ch > 0) __syncthreads();
        {
            uint4 h, l;
            split4(ra0, h, l);
            *(uint4*)&Ah[ar][ac] = h;     *(uint4*)&Al[ar][ac] = l;
            split4(ra1, h, l);
            *(uint4*)&Ah[ar][ac + 4] = h; *(uint4*)&Al[ar][ac + 4] = l;
            split4(rb0, h, l);
            *(uint4*)&Bh[br][bc] = h;     *(uint4*)&Bl[br][bc] = l;
            split4(rb1, h, l);
            *(uint4*)&Bh[br][bc + 4] = h; *(uint4*)&Bl[br][bc + 4] = l;
        }
        __syncthreads();
        if (ch + 1 < nc) {
            int k0 = (ch + 1) * 32;
            ra0 = *(const float4*)&A[(size_t)(bm + ar) * K + k0 + ac];
            ra1 = *(const float4*)&A[(size_t)(bm + ar) * K + k0 + ac + 4];
            rb0 = *(const float4*)&B[(size_t)(k0 + br) * N + bn + bc];
            rb1 = *(const float4*)&B[(size_t)(k0 + br) * N + bn + bc + 4];
        }
#pragma unroll
        for (int ks = 0; ks < 4; ks++) {
            int k8 = ks * 8;
            uint32_t ah[2][4], al[2][4], bh[2][2], bl[2][2];
#pragma unroll
            for (int ma = 0; ma < 2; ma++) {
                int m0 = wm * 32 + ma * 16 + gid;
                ah[ma][0] = Ah[m0][k8 + tig];     al[ma][0] = Al[m0][k8 + tig];
                ah[ma][1] = Ah[m0 + 8][k8 + tig]; al[ma][1] = Al[m0 + 8][k8 + tig];
                ah[ma][2] = Ah[m0][k8 + tig + 4]; al[ma][2] = Al[m0][k8 + tig + 4];
                ah[ma][3] = Ah[m0 + 8][k8 + tig + 4]; al[ma][3] = Al[m0 + 8][k8 + tig + 4];
            }
#pragma unroll
            for (int na = 0; na < 2; na++) {
                int n0 = wn * 16 + na * 8 + gid;
                bh[na][0] = Bh[k8 + tig][n0];     bl[na][0] = Bl[k8 + tig][n0];
                bh[na][1] = Bh[k8 + tig + 4][n0]; bl[na][1] = Bl[k8 + tig + 4][n0];
            }
#pragma unroll
            for (int ma = 0; ma < 2; ma++)
#pragma unroll
                for (int na = 0; na < 2; na++)
                    mma3(c[ma][na], ah[ma], al[ma], bh[na], bl[na]);
        }
    }

#pragma unroll
    for (int ma = 0; ma < 2; ma++)
#pragma unroll
        for (int na = 0; na < 2; na++) {
            int row = bm + wm * 32 + ma * 16 + gid;
            int col = bn + wn * 16 + na * 8 + 2 * tig;
            float2 bv = *(const float2*)&bias[col];
            float2 o0; o0.x = c[ma][na][0] + bv.x; o0.y = c[ma][na][1] + bv.y;
            float2 o1; o1.x = c[ma][na][2] + bv.x; o1.y = c[ma][na][3] + bv.y;
            *(float2*)&C[(size_t)row * N + col]       = o0;
            *(float2*)&C[(size_t)(row + 8) * N + col] = o1;
        }
}

// ---------- K2 tensor: qk[s][h][j] = Q_h[s,:] . Wk_h[j,:]  (K=32) -------
__global__ void __launch_bounds__(256)
k_qk_tf32(const float* __restrict__ Wkv, const float* __restrict__ bkv) {
    __shared__ uint32_t Ah[64][36], Al[64][36];   // q slice  [s][d]
    __shared__ uint32_t Nh[64][36], Nl[64][36];   // Wk slice [j][d]
    int t = threadIdx.x;
    int lane = t & 31, w = t >> 5;
    int gid = lane >> 2, tig = lane & 3;
    int wm = w & 1, wn = w >> 1;
    int bm = blockIdx.x * 64, bnj = blockIdx.y * 64, h = blockIdx.z;
    int r = t >> 2, cq = (t & 3) * 8;

    {
        float4 v0 = *(const float4*)&g_q[(size_t)(bm + r) * H_DIM + h * HD + cq];
        float4 v1 = *(const float4*)&g_q[(size_t)(bm + r) * H_DIM + h * HD + cq + 4];
        uint4 hh, ll;
        split4(v0, hh, ll); *(uint4*)&Ah[r][cq] = hh;     *(uint4*)&Al[r][cq] = ll;
        split4(v1, hh, ll); *(uint4*)&Ah[r][cq + 4] = hh; *(uint4*)&Al[r][cq + 4] = ll;
        float4 w0 = *(const float4*)&Wkv[(size_t)(bnj + r) * 512 + h * HD + cq];
        float4 w1 = *(const float4*)&Wkv[(size_t)(bnj + r) * 512 + h * HD + cq + 4];
        split4(w0, hh, ll); *(uint4*)&Nh[r][cq] = hh;     *(uint4*)&Nl[r][cq] = ll;
        split4(w1, hh, ll); *(uint4*)&Nh[r][cq + 4] = hh; *(uint4*)&Nl[r][cq + 4] = ll;
    }
    __syncthreads();

    float c[2][2][4] = {};
#pragma unroll
    for (int ks = 0; ks < 4; ks++) {
        int k8 = ks * 8;
        uint32_t ah[2][4], al[2][4], bh[2][2], bl[2][2];
#pragma unroll
        for (int ma = 0; ma < 2; ma++) {
            int m0 = wm * 32 + ma * 16 + gid;
            ah[ma][0] = Ah[m0][k8 + tig];         al[ma][0] = Al[m0][k8 + tig];
            ah[ma][1] = Ah[m0 + 8][k8 + tig];     al[ma][1] = Al[m0 + 8][k8 + tig];
            ah[ma][2] = Ah[m0][k8 + tig + 4];     al[ma][2] = Al[m0][k8 + tig + 4];
            ah[ma][3] = Ah[m0 + 8][k8 + tig + 4]; al[ma][3] = Al[m0 + 8][k8 + tig + 4];
        }
#pragma unroll
        for (int na = 0; na < 2; na++) {
            int n0 = wn * 16 + na * 8 + gid;
            bh[na][0] = Nh[n0][k8 + tig];     bl[na][0] = Nl[n0][k8 + tig];
            bh[na][1] = Nh[n0][k8 + tig + 4]; bl[na][1] = Nl[n0][k8 + tig + 4];
        }
#pragma unroll
        for (int ma = 0; ma < 2; ma++)
#pragma unroll
            for (int na = 0; na < 2; na++)
                mma3(c[ma][na], ah[ma], al[ma], bh[na], bl[na]);
    }

#pragma unroll
    for (int ma = 0; ma < 2; ma++)
#pragma unroll
        for (int na = 0; na < 2; na++) {
            int srow = bm + wm * 32 + ma * 16 + gid;
            int col  = bnj + wn * 16 + na * 8 + 2 * tig;
            float2 o0; o0.x = c[ma][na][0]; o0.y = c[ma][na][1];
            float2 o1; o1.x = c[ma][na][2]; o1.y = c[ma][na][3];
            *(float2*)&g_qk[(size_t)srow * (NH * D_DIM) + h * D_DIM + col]       = o0;
            *(float2*)&g_qk[(size_t)(srow + 8) * (NH * D_DIM) + h * D_DIM + col] = o1;
        }

    if (blockIdx.y == 0 && t < 64) {
        int s = bm + t;
        float acc = 0.f;
#pragma unroll
        for (int d = 0; d < HD; d++)
            acc += g_q[(size_t)s * H_DIM + h * HD + d] * bkv[h * HD + d];
        g_qb[s * NH + h] = acc;
    }
}

// ---------- K4 tensor: pooled_h = Ahat_h[64x256] @ Wv_h[256x32] ---------
__global__ void __launch_bounds__(256)
k_pool_tf32(const float* __restrict__ Wkv, const float* __restrict__ bkv) {
    __shared__ uint32_t Ah[64][36], Al[64][36];
    __shared__ uint32_t Bh[32][40], Bl[32][40];
    int t = threadIdx.x;
    int lane = t & 31, w = t >> 5;
    int gid = lane >> 2, tig = lane & 3;
    int wm = w & 3, wn = w >> 2;
    int bm = blockIdx.x * 64, h = blockIdx.y;
    int arr = t >> 2, acq = (t & 3) * 8;
    int bkk = t >> 3, bn4 = (t & 7) * 4;

    const float* Abase = g_Ahat + (size_t)bm * (NH * D_DIM) + h * D_DIM;
    float c[2][4] = {};
    float4 ra0, ra1, rb;

    ra0 = *(const float4*)&Abase[(size_t)arr * (NH * D_DIM) + acq];
    ra1 = *(const float4*)&Abase[(size_t)arr * (NH * D_DIM) + acq + 4];
    rb  = *(const float4*)&Wkv[(size_t)bkk * 512 + 256 + h * HD + bn4];

    for (int ch = 0; ch < 8; ch++) {
        if (ch > 0) __syncthreads();
        {
            uint4 hh, ll;
            split4(ra0, hh, ll);
            *(uint4*)&Ah[arr][acq] = hh;     *(uint4*)&Al[arr][acq] = ll;
            split4(ra1, hh, ll);
            *(uint4*)&Ah[arr][acq + 4] = hh; *(uint4*)&Al[arr][acq + 4] = ll;
            split4(rb, hh, ll);
            *(uint4*)&Bh[bkk][bn4] = hh;     *(uint4*)&Bl[bkk][bn4] = ll;
        }
        __syncthreads();
        if (ch + 1 < 8) {
            int k0 = (ch + 1) * 32;
            ra0 = *(const float4*)&Abase[(size_t)arr * (NH * D_DIM) + k0 + acq];
            ra1 = *(const float4*)&Abase[(size_t)arr * (NH * D_DIM) + k0 + acq + 4];
            rb  = *(const float4*)&Wkv[(size_t)(k0 + bkk) * 512 + 256 + h * HD + bn4];
        }
#pragma unroll
        for (int ks = 0; ks < 4; ks++) {
            int k8 = ks * 8;
            uint32_t ah[4], al[4], bh[2][2], bl[2][2];
            int m0 = wm * 16 + gid;
            ah[0] = Ah[m0][k8 + tig];         al[0] = Al[m0][k8 + tig];
            ah[1] = Ah[m0 + 8][k8 + tig];     al[1] = Al[m0 + 8][k8 + tig];
            ah[2] = Ah[m0][k8 + tig + 4];     al[2] = Al[m0][k8 + tig + 4];
            ah[3] = Ah[m0 + 8][k8 + tig + 4]; al[3] = Al[m0 + 8][k8 + tig + 4];
#pragma unroll
            for (int na = 0; na < 2; na++) {
                int n0 = wn * 16 + na * 8 + gid;
                bh[na][0] = Bh[k8 + tig][n0];     bl[na][0] = Bl[k8 + tig][n0];
                bh[na][1] = Bh[k8 + tig + 4][n0]; bl[na][1] = Bl[k8 + tig + 4][n0];
            }
#pragma unroll
            for (int na = 0; na < 2; na++)
                mma3(c[na], ah, al, bh[na], bl[na]);
        }
    }

#pragma unroll
    for (int na = 0; na < 2; na++) {
        int row = bm + wm * 16 + gid;
        int col = wn * 16 + na * 8 + 2 * tig;
        float2 bv = *(const float2*)&bkv[256 + h * HD + col];
        bool ne0 = g_off[row + 1] > g_off[row];
        bool ne1 = g_off[row + 9] > g_off[row + 8];
        float2 o0, o1;
        o0.x = c[na][0] + (ne0 ? bv.x : 0.f); o0.y = c[na][1] + (ne0 ? bv.y : 0.f);
        o1.x = c[na][2] + (ne1 ? bv.x : 0.f); o1.y = c[na][3] + (ne1 ? bv.y : 0.f);
        *(float2*)&g_pooled[(size_t)row * H_DIM + h * HD + col]       = o0;
        *(float2*)&g_pooled[(size_t)(row + 8) * H_DIM + h * HD + col] = o1;
    }
}

// ---------------- K3: streaming softmax-pool accumulation ---------------
// One block per sample; 4 blocks/SM (51.6KB smem, <=64 regs). cp.async
// per-16B loads. BOTH matrix phases tensorized:
//  * score: per-warp j-slice K=32 as mma.m16n8k8 M=e(32) N=h(8) K=j;
//    E A-frags + qk B-frags mask-split inline; partials -> sPart; the
//    reduce/exp phase is unchanged.
//  * A-update: M=j(16x2) N=h(8) K=e(8x4) as in R10.
// No running max (scores O(+-8), exp fp32-safe; shift cancels exactly).
// Partial tiles: sE rows [T,32) zero-filled (0-products, never NaN).
// Smem floats: sQK[0,2080) sE[2080,10400) sPart[10400,12496)
//              sP[12496,12880) sD[12880,12888) sQBs[12888,12896)
#define ATTN_SMEM_FLOATS (12896)
#define SE_STRIDE 260

__global__ void __launch_bounds__(256, 4)
k_attn(const float* __restrict__ emb, float scale) {
    extern __shared__ float dyn[];
    float* sQK   = dyn;
    float* sE    = dyn + 2080;
    float* sPart = dyn + 10400;
    float* sP    = dyn + 12496;
    float* sD    = dyn + 12880;
    float* sQBs  = dyn + 12888;

    int s = blockIdx.x;
    int t = threadIdx.x;
    int lane = t & 31, w = t >> 5;
    int gid = lane >> 2, tig = lane & 3;

    int start = g_off[s], end = g_off[s + 1];

    // prefetch first emb tile (overlaps qk load)
    if (start < end) {
        int T = min(32, end - start);
        for (int i = t; i < T * 64; i += 256) {
            int e = i >> 6, j4 = (i & 63) * 4;
            cpa16(&sE[e * SE_STRIDE + j4],
                  emb + (size_t)(start + e) * D_DIM + j4);
        }
    }
    CPA_COMMIT();

    const float* qkp = g_qk + (size_t)s * (NH * D_DIM);
    for (int i = t; i < (NH * D_DIM) / 4; i += 256) {
        float4 v = *(const float4*)(qkp + i * 4);
        int h = i >> 6, j = (i * 4) & 255;
        *(float4*)&sQK[h * SE_STRIDE + j] = v;
    }
    if (t < NH) sQBs[t] = g_qb[s * NH + t];

    // A accumulators: c[ma][0..3] = A at (j = 32w + 16ma + gid (+8), h = 2tig (+1))
    float c[2][4] = {};
    float d_w = 0.f;
    int j0 = w * 32;
    __syncthreads();   // sQK ready

    for (int t0 = start; t0 < end; t0 += 32) {
        int T = min(32, end - t0);

        CPA_WAIT0();
        __syncthreads();   // sE full

        if (T < 32) {      // zero tail rows so 0*garbage can't make NaN in mma
            for (int i = t; i < (32 - T) * 64; i += 256) {
                int e = T + (i >> 6), j4 = (i & 63) * 4;
                *(float4*)&sE[e * SE_STRIDE + j4] = make_float4(0.f, 0.f, 0.f, 0.f);
            }
            __syncthreads();   // T uniform across block
        }

        // ---- score partials via tensor cores: warp w covers K-slice
        //      j in [j0, j0+32); M=e (2 atoms), N=h (8). Conflict-free
        //      frag LDS (bank = 4*gid+tig+const).
        {
            float cs[2][4] = {};
#pragma unroll
            for (int ks = 0; ks < 4; ks++) {
                int jk = j0 + ks * 8;
                uint32_t bh[2], bl[2];
                tf32_split(sQK[gid * SE_STRIDE + jk + tig],     bh[0], bl[0]);
                tf32_split(sQK[gid * SE_STRIDE + jk + tig + 4], bh[1], bl[1]);
#pragma unroll
                for (int ma = 0; ma < 2; ma++) {
                    int e0 = ma * 16 + gid;
                    uint32_t ah[4], al[4];
                    tf32_split(sE[e0 * SE_STRIDE + jk + tig],           ah[0], al[0]);
                    tf32_split(sE[(e0 + 8) * SE_STRIDE + jk + tig],     ah[1], al[1]);
                    tf32_split(sE[e0 * SE_STRIDE + jk + tig + 4],       ah[2], al[2]);
                    tf32_split(sE[(e0 + 8) * SE_STRIDE + jk + tig + 4], ah[3], al[3]);
                    mma3(cs[ma], ah, al, bh, bl);
                }
            }
#pragma unroll
            for (int ma = 0; ma < 2; ma++) {
                int e0 = ma * 16 + gid;
                sPart[e0 * 65 + (2 * tig) * 8 + w]           = cs[ma][0];
                sPart[e0 * 65 + (2 * tig + 1) * 8 + w]       = cs[ma][1];
                sPart[(e0 + 8) * 65 + (2 * tig) * 8 + w]     = cs[ma][2];
                sPart[(e0 + 8) * 65 + (2 * tig + 1) * 8 + w] = cs[ma][3];
            }
        }
        __syncthreads();

        // ---- reduce partials + exp (no max shift): thread (lane=e, w=h)
        float p = 0.f;
        if (lane < T) {
            float sum = 0.f;
#pragma unroll
            for (int i = 0; i < 8; i++) sum += sPart[lane * 65 + w * 8 + i];
            p = __expf(scale * (sum + sQBs[w]));
        }
        sP[lane * 12 + w] = p;
        float ps = p;
#pragma unroll
        for (int o = 16; o; o >>= 1) ps += __shfl_xor_sync(0xffffffffu, ps, o);
        d_w += ps;
        __syncthreads();

        // ---- A update via tensor cores: D[16j x 8h] += E^T-frag @ P-frag
#pragma unroll
        for (int ks = 0; ks < 4; ks++) {
            int e0 = 8 * ks + tig;
            uint32_t bh[2], bl[2];
            tf32_split(sP[e0 * 12 + gid],       bh[0], bl[0]);
            tf32_split(sP[(e0 + 4) * 12 + gid], bh[1], bl[1]);
#pragma unroll
            for (int ma = 0; ma < 2; ma++) {
                int jb = j0 + ma * 16 + gid;
                uint32_t ah[4], al[4];
                tf32_split(sE[e0 * SE_STRIDE + jb],           ah[0], al[0]);
                tf32_split(sE[e0 * SE_STRIDE + jb + 8],       ah[1], al[1]);
                tf32_split(sE[(e0 + 4) * SE_STRIDE + jb],     ah[2], al[2]);
                tf32_split(sE[(e0 + 4) * SE_STRIDE + jb + 8], ah[3], al[3]);
                mma3(c[ma], ah, al, bh, bl);
            }
        }
        __syncthreads();   // all sE reads done; safe to refill

        // issue next tile's loads
        if (t0 + 32 < end) {
            int Tn = min(32, end - (t0 + 32));
            for (int i = t; i < Tn * 64; i += 256) {
                int e = i >> 6, j4 = (i & 63) * 4;
                cpa16(&sE[e * SE_STRIDE + j4],
                      emb + (size_t)(t0 + 32 + e) * D_DIM + j4);
            }
        }
        CPA_COMMIT();
    }

    if (lane == 0) sD[w] = d_w;
    __syncthreads();

    // epilogue: c[ma] holds (j = j0 + 16ma + gid (+8), h = 2tig (+1))
    {
        float dh0 = sD[2 * tig],     rdh0 = (dh0 > 0.f) ? (1.0f / dh0) : 0.f;
        float dh1 = sD[2 * tig + 1], rdh1 = (dh1 > 0.f) ? (1.0f / dh1) : 0.f;
        float* outp = g_Ahat + (size_t)s * (NH * D_DIM);
#pragma unroll
        for (int ma = 0; ma < 2; ma++) {
            int j = j0 + ma * 16 + gid;
            outp[(2 * tig) * D_DIM + j]         = c[ma][0] * rdh0;
            outp[(2 * tig + 1) * D_DIM + j]     = c[ma][1] * rdh1;
            outp[(2 * tig) * D_DIM + j + 8]     = c[ma][2] * rdh0;
            outp[(2 * tig + 1) * D_DIM + j + 8] = c[ma][3] * rdh1;
        }
    }
}

// ---------------- launch ----------------
extern "C" void kernel_launch(void* const* d_in, const int* in_sizes, int n_in,
                              void* d_out, int out_size) {
    const float* queries = (const float*)d_in[0];
    const float* emb     = (const float*)d_in[1];
    const int*   map     = (const int*)  d_in[2];
    // num_samples may or may not be materialized as a device input
    int base = (n_in >= 10 && in_sizes[3] < 16) ? 4 : 3;
    const float* Wq  = (const float*)d_in[base + 0];
    const float* bq  = (const float*)d_in[base + 1];
    const float* Wkv = (const float*)d_in[base + 2];
    const float* bkv = (const float*)d_in[base + 3];
    const float* Wo  = (const float*)d_in[base + 4];
    const float* bo  = (const float*)d_in[base + 5];
    float* out = (float*)d_out;

    int S = in_sizes[0] / D_DIM;     // 4096
    int N = in_sizes[1] / D_DIM;     // 262144
    float scale = 0.17677669529663687f;   // 1/sqrt(32)

    float* dq      = nullptr; cudaGetSymbolAddress((void**)&dq,      g_q);
    float* dpooled = nullptr; cudaGetSymbolAddress((void**)&dpooled, g_pooled);

    cudaFuncSetAttribute(k_attn, cudaFuncAttributeMaxDynamicSharedMemorySize,
                         ATTN_SMEM_FLOATS * 4);

    // K0: segment offsets
    k_offsets<<<(S + 1 + 255) / 256, 256>>>(map, N, S);
    // K1: q projection (tensor core, 3xTF32)
    {
        dim3 grid(S / 64, H_DIM / 64);
        k_gemm_tf32<<<grid, 256>>>(queries, Wq, bq, dq, S, D_DIM, H_DIM);
    }
    // K2: qk/qb precompute (tensor core)
    {
        dim3 grid(S / 64, D_DIM / 64, NH);
        k_qk_tf32<<<grid, 256>>>(Wkv, bkv);
    }
    // K3: streaming attention accumulation (both phases tensorized)
    k_attn<<<S, 256, ATTN_SMEM_FLOATS * 4>>>(emb, scale);
    // K4: pooled projection through Wv (tensor core)
    {
        dim3 grid(S / 64, NH);
        k_pool_tf32<<<grid, 256>>>(Wkv, bkv);
    }
    // K5: output projection (tensor core, 3xTF32)
    {
        dim3 grid(S / 64, H_DIM / 64);
        k_gemm_tf32<<<grid, 256>>>(dpooled, Wo, bo, out, S, H_DIM, H_DIM);
    }
}